// round 4
// baseline (speedup 1.0000x reference)
#include <cuda_runtime.h>
#include <cstdint>

#define NDIM 256
#define FDIM 32
#define KDIM 8
#define XS_STRIDE 260
#define SB_STRIDE 72

// Precomputed 0.5 * W (symmetric, zero diagonal), tf32-rounded, fp32 container.
__device__ __align__(16) float g_S[NDIM * NDIM];

// ---------------------------------------------------------------------------
// helpers
// ---------------------------------------------------------------------------
__device__ __forceinline__ uint32_t f2tf(float x) {
    uint32_t r;
    asm("cvt.rna.tf32.f32 %0, %1;" : "=r"(r) : "f"(x));
    return r;
}

__device__ __forceinline__ void cp16(void* smem_dst, const void* gsrc) {
    uint32_t d = (uint32_t)__cvta_generic_to_shared(smem_dst);
    asm volatile("cp.async.cg.shared.global [%0], [%1], 16;\n" :: "r"(d), "l"(gsrc));
}
__device__ __forceinline__ void cp_commit() {
    asm volatile("cp.async.commit_group;\n");
}
template <int N>
__device__ __forceinline__ void cp_wait() {
    asm volatile("cp.async.wait_group %0;\n" :: "n"(N));
}

__device__ __forceinline__ void mma8(float* c, const uint32_t* a, uint32_t b0, uint32_t b1) {
    asm volatile(
        "mma.sync.aligned.m16n8k8.row.col.f32.tf32.tf32.f32 "
        "{%0,%1,%2,%3}, {%4,%5,%6,%7}, {%8,%9}, {%0,%1,%2,%3};"
        : "+f"(c[0]), "+f"(c[1]), "+f"(c[2]), "+f"(c[3])
        : "r"(a[0]), "r"(a[1]), "r"(a[2]), "r"(a[3]), "r"(b0), "r"(b1));
}

// ---------------------------------------------------------------------------
// Kernel 1: build S[i][j] = (i==j) ? 0 : 0.5 * sum_k v[i, f(j), k] * v[j, f(i), k]
// ---------------------------------------------------------------------------
__global__ void build_S_kernel(const float* __restrict__ v, const int* __restrict__ fidx) {
    int i = blockIdx.x;
    int j = threadIdx.x;
    int fi = fidx[i];
    int fj = fidx[j];
    const float4* vi = reinterpret_cast<const float4*>(v + i * (FDIM * KDIM) + fj * KDIM);
    const float4* vj = reinterpret_cast<const float4*>(v + j * (FDIM * KDIM) + fi * KDIM);
    float4 a0 = vi[0], a1 = vi[1], b0 = vj[0], b1 = vj[1];
    float s = a0.x * b0.x + a0.y * b0.y + a0.z * b0.z + a0.w * b0.w
            + a1.x * b1.x + a1.y * b1.y + a1.z * b1.z + a1.w * b1.w;
    s = (i == j) ? 0.0f : 0.5f * s;
    g_S[i * NDIM + j] = __uint_as_float(f2tf(s));
}

// ---------------------------------------------------------------------------
// Kernel 2: fused  out[b] = b_lin + sum_n x[b,n] * (w_lin[n] + (X S)[b,n])
// CTA: 128 rows of X, 256 threads = 8 warps arranged 4(M) x 2(N).
// N processed in 4 chunks of 64; K=256 streamed in 32-row S tiles (cp.async x2 buf).
// ---------------------------------------------------------------------------
__device__ __forceinline__ void load_stile(float* dst, int kt, int ncb, int tid) {
    int r = tid >> 3;           // 0..31
    int c = (tid & 7) * 8;      // 0..56
    const float* src = g_S + (kt * 32 + r) * NDIM + ncb + c;
    cp16(&dst[r * SB_STRIDE + c], src);
    cp16(&dst[r * SB_STRIDE + c + 4], src + 4);
}

__global__ __launch_bounds__(256, 1)
void ffm_main_kernel(const float* __restrict__ x,
                     const float* __restrict__ w_lin,
                     const float* __restrict__ b_lin,
                     float* __restrict__ out) {
    extern __shared__ float smem[];
    float* XS = smem;                                // 128 * 260
    float* SB = XS + 128 * XS_STRIDE;                // 2 * 32 * 72
    float* WS = SB + 2 * 32 * SB_STRIDE;             // 256
    float* SR = WS + 256;                            // 128

    const int tid   = threadIdx.x;
    const int lane  = tid & 31;
    const int warp  = tid >> 5;
    const int warpM = warp & 3;      // 0..3 -> M base = warpM*32
    const int warpN = warp >> 2;     // 0..1 -> N base = warpN*32 within 64-chunk
    const int grp   = lane >> 2;     // 0..7
    const int tig   = lane & 3;      // 0..3
    const int gm    = blockIdx.x * 128;

    // Stage X tile (128 x 256 fp32) into SMEM via cp.async.
    {
        const float* xbase = x + (size_t)gm * NDIM;
        #pragma unroll
        for (int it = 0; it < 32; ++it) {
            int idx = tid + it * 256;      // 0..8191 = 128 rows * 64 float4
            int row = idx >> 6;
            int c4  = idx & 63;
            cp16(&XS[row * XS_STRIDE + c4 * 4], xbase + row * NDIM + c4 * 4);
        }
    }
    WS[tid & 255] = w_lin[tid & 255];
    if (tid < 128) SR[tid] = 0.0f;

    float p[4] = {0.f, 0.f, 0.f, 0.f};   // per-row partials: [mf*2 + hi]

    for (int nc = 0; nc < 4; ++nc) {
        const int ncb = nc * 64;

        float acc[2][4][4];
        #pragma unroll
        for (int mf = 0; mf < 2; ++mf)
            #pragma unroll
            for (int nt = 0; nt < 4; ++nt)
                #pragma unroll
                for (int r = 0; r < 4; ++r) acc[mf][nt][r] = 0.0f;

        // prologue: first S tile of this chunk
        load_stile(SB, 0, ncb, tid);
        cp_commit();

        for (int kt = 0; kt < 8; ++kt) {
            if (kt < 7) {
                load_stile(SB + ((kt + 1) & 1) * 32 * SB_STRIDE, kt + 1, ncb, tid);
                cp_commit();
                cp_wait<1>();
            } else {
                cp_wait<0>();
            }
            __syncthreads();

            const float* Sb = SB + (kt & 1) * 32 * SB_STRIDE;
            const int kg = kt * 32;

            #pragma unroll
            for (int ks = 0; ks < 4; ++ks) {
                const int k0 = ks * 8;
                uint32_t a[2][4];
                #pragma unroll
                for (int mf = 0; mf < 2; ++mf) {
                    const float* xr = XS + (warpM * 32 + mf * 16 + grp) * XS_STRIDE + kg + k0 + tig;
                    a[mf][0] = f2tf(xr[0]);
                    a[mf][2] = f2tf(xr[4]);
                    a[mf][1] = f2tf(xr[8 * XS_STRIDE]);
                    a[mf][3] = f2tf(xr[8 * XS_STRIDE + 4]);
                }
                #pragma unroll
                for (int nt = 0; nt < 4; ++nt) {
                    const int col = warpN * 32 + nt * 8 + grp;
                    uint32_t b0 = __float_as_uint(Sb[(k0 + tig) * SB_STRIDE + col]);
                    uint32_t b1 = __float_as_uint(Sb[(k0 + tig + 4) * SB_STRIDE + col]);
                    mma8(acc[0][nt], a[0], b0, b1);
                    mma8(acc[1][nt], a[1], b0, b1);
                }
            }
            __syncthreads();
        }

        // epilogue for this N-chunk: p[row] += (Z + w) * x
        #pragma unroll
        for (int mf = 0; mf < 2; ++mf)
            #pragma unroll
            for (int nt = 0; nt < 4; ++nt)
                #pragma unroll
                for (int r = 0; r < 4; ++r) {
                    int col = ncb + warpN * 32 + nt * 8 + tig * 2 + (r & 1);
                    int row = warpM * 32 + mf * 16 + grp + ((r >> 1) << 3);
                    p[mf * 2 + (r >> 1)] += (acc[mf][nt][r] + WS[col]) * XS[row * XS_STRIDE + col];
                }
    }

    // reduce partials across the 4 lanes of each quad (they hold disjoint cols)
    #pragma unroll
    for (int i = 0; i < 4; ++i) {
        p[i] += __shfl_xor_sync(0xffffffffu, p[i], 1);
        p[i] += __shfl_xor_sync(0xffffffffu, p[i], 2);
    }
    if (tig == 0) {
        #pragma unroll
        for (int i = 0; i < 4; ++i) {
            int row = warpM * 32 + (i >> 1) * 16 + grp + (i & 1) * 8;
            atomicAdd(&SR[row], p[i]);   // 2 warpN contributions per row
        }
    }
    __syncthreads();

    if (tid < 128) out[gm + tid] = b_lin[0] + SR[tid];
}

// ---------------------------------------------------------------------------
// launch
// ---------------------------------------------------------------------------
extern "C" void kernel_launch(void* const* d_in, const int* in_sizes, int n_in,
                              void* d_out, int out_size) {
    const float* x      = (const float*)d_in[0];
    const float* w_lin  = (const float*)d_in[1];
    const float* b_lin  = (const float*)d_in[2];
    const float* v      = (const float*)d_in[3];
    const int*   fidx   = (const int*)d_in[4];
    float*       out    = (float*)d_out;

    // out_size is unambiguously B (one scalar per batch row).
    const int Bn = out_size;

    build_S_kernel<<<NDIM, NDIM>>>(v, fidx);

    const int smem_bytes = (128 * XS_STRIDE + 2 * 32 * SB_STRIDE + 256 + 128) * 4; // 153088
    cudaFuncSetAttribute(ffm_main_kernel, cudaFuncAttributeMaxDynamicSharedMemorySize, smem_bytes);
    ffm_main_kernel<<<Bn / 128, 256, smem_bytes>>>(x, w_lin, b_lin, out);
}